// round 5
// baseline (speedup 1.0000x reference)
#include <cuda_runtime.h>
#include <cstdint>

#define N_SAMP 16
#define C_TOT 256
#define KK 8
#define M_IN 63
#define M_OUT 56
#define CHUNKS 16          // channel chunks (16 channels = 8 pairs each)
#define PAIRS 8
#define THREADS 224        // 56 cols x 4 row-bands
#define R_ROWS 14
#define OUT_PER_N (M_OUT * M_OUT)   // 3136
#define OUT_TOTAL (N_SAMP * OUT_PER_N)
#define PLANE 3969         // 63*63 floats per channel
#define RAW_FLOATS (2 * PLANE)      // one raw pair buffer: 7938 floats
#define XS_F2 (M_IN * 64)           // 63 rows x 64 float2 (col 63 pad)

typedef unsigned long long ull;

__device__ float g_partial[CHUNKS * OUT_TOTAL];   // 3.2 MB scratch

__device__ __forceinline__ ull fma2(ull a, ull b, ull c) {
    ull d;
    asm("fma.rn.f32x2 %0, %1, %2, %3;" : "=l"(d) : "l"(a), "l"(b), "l"(c));
    return d;
}
__device__ __forceinline__ float fast_sqrt(float v) {
    float r;
    asm("sqrt.approx.f32 %0, %1;" : "=f"(r) : "f"(v));
    return r;
}
__device__ __forceinline__ void cp_async8(uint32_t saddr, const void* gaddr) {
    asm volatile("cp.async.ca.shared.global [%0], [%1], 8;\n"
                 :: "r"(saddr), "l"(gaddr));
}
__device__ __forceinline__ void cp_commit() {
    asm volatile("cp.async.commit_group;\n" ::: "memory");
}
__device__ __forceinline__ void cp_wait0() {
    asm volatile("cp.async.wait_group 0;\n" ::: "memory");
}
__device__ __forceinline__ void cp_wait1() {
    asm volatile("cp.async.wait_group 1;\n" ::: "memory");
}

// Issue async copy of one channel pair (7938 floats, 8B-aligned) into raw buf.
__device__ __forceinline__ void issue_pair(uint32_t raw_s, const float* xc, int tid)
{
    #pragma unroll
    for (int it = 0; it < 18; it++) {
        int i = tid + it * THREADS;            // 8-byte unit index, 3969 total
        if (i < PLANE)
            cp_async8(raw_s + i * 8, (const char*)xc + i * 8);
    }
    cp_commit();
}

// raw (2 channel planes) -> xs interleaved sqrt pairs
__device__ __forceinline__ void convert_pair(const float* __restrict__ raw,
                                             float2* __restrict__ xs, int tid)
{
    #pragma unroll
    for (int it = 0; it < 18; it++) {
        int pos = tid + it * THREADS;
        if (pos < PLANE) {
            float f0 = raw[pos];
            float f1 = raw[PLANE + pos];
            int row = pos / M_IN;
            int col = pos - row * M_IN;
            xs[row * 64 + col] = make_float2(fast_sqrt(f0), fast_sqrt(f1));
        }
    }
}

__global__ __launch_bounds__(THREADS, 2)
void conv_partial_kernel(const float* __restrict__ z,
                         const float* __restrict__ x,
                         const float* __restrict__ w)
{
    extern __shared__ float smem_raw[];
    float2* xs   = reinterpret_cast<float2*>(smem_raw);          // 32256 B
    float*  raw0 = smem_raw + 2 * XS_F2;                         // 31752 B
    float*  raw1 = raw0 + RAW_FLOATS;                            // 31752 B
    float2* zs   = reinterpret_cast<float2*>(raw1 + RAW_FLOATS); // 4096 B

    const int n     = blockIdx.x;
    const int chunk = blockIdx.y;
    const int tid   = threadIdx.x;
    const int j     = tid % M_OUT;
    const int i0    = (tid / M_OUT) * R_ROWS;

    const int cbase = chunk * (2 * PAIRS);
    const float* xn = x + (size_t)n * C_TOT * (M_IN * M_IN);
    const float* zn = z + (size_t)n * C_TOT * (KK * KK);

    const uint32_t raw0_s = (uint32_t)__cvta_generic_to_shared(raw0);
    const uint32_t raw1_s = (uint32_t)__cvta_generic_to_shared(raw1);

    // Pipeline prologue: pair0 -> raw0, pair1 -> raw1 (issued first, so the
    // DRAM fetch runs under the z staging below).
    issue_pair(raw0_s, xn + (size_t)cbase * PLANE, tid);
    issue_pair(raw1_s, xn + (size_t)(cbase + 2) * PLANE, tid);

    // Stage all z pairs once: zs[pair][p*8+q] = (w0*sqrt(z0), w1*sqrt(z1))
    for (int idx = tid; idx < PAIRS * KK * KK; idx += THREADS) {
        int cp  = idx >> 6;
        int tap = idx & 63;
        int c   = cbase + 2 * cp;
        float w0 = w[c], w1 = w[c + 1];
        float a = fast_sqrt(zn[(size_t)c * 64 + tap]);
        float b = fast_sqrt(zn[(size_t)(c + 1) * 64 + tap]);
        zs[idx] = make_float2(w0 * a, w1 * b);
    }

    cp_wait1();                       // this thread's raw0 copies complete
    __syncthreads();                  // make ALL threads' raw0 copies visible
    convert_pair(raw0, xs, tid);
    __syncthreads();

    ull acc[R_ROWS];
    #pragma unroll
    for (int r = 0; r < R_ROWS; r++) acc[r] = 0ULL;

    #pragma unroll 1
    for (int cp = 0; cp < PAIRS; cp++) {
        const float2* xrow = xs + i0 * 64 + j;
        const float2* zsp  = zs + cp * (KK * KK);

        #pragma unroll
        for (int q = 0; q < KK; q++) {
            ull zq[KK];
            #pragma unroll
            for (int p = 0; p < KK; p++)
                zq[p] = *reinterpret_cast<const ull*>(&zsp[p * KK + q]);

            #pragma unroll
            for (int t = 0; t < R_ROWS + KK - 1; t++) {
                ull xv = *reinterpret_cast<const ull*>(xrow + t * 64 + q);
                #pragma unroll
                for (int r = 0; r < R_ROWS; r++) {
                    const int p = t - r;
                    if (p >= 0 && p < KK)
                        acc[r] = fma2(xv, zq[p], acc[r]);
                }
            }
        }

        if (cp < PAIRS - 1) {
            const float* nraw = (cp & 1) ? raw0 : raw1;     // buf[(cp+1)&1]
            const uint32_t is = (cp & 1) ? raw1_s : raw0_s; // buf[cp&1] for cp+2
            cp_wait0();               // pair cp+1's copies (this thread) done
            __syncthreads();          // visibility across threads; xs reads done
            convert_pair(nraw, xs, tid);
            if (cp < PAIRS - 2)
                issue_pair(is, xn + (size_t)(cbase + 2 * (cp + 2)) * PLANE, tid);
            __syncthreads();          // xs ready for next compute
        }
    }

    float* outp = g_partial + (size_t)(chunk * N_SAMP + n) * OUT_PER_N;
    #pragma unroll
    for (int r = 0; r < R_ROWS; r++) {
        float lo = __uint_as_float((unsigned)(acc[r] & 0xFFFFFFFFull));
        float hi = __uint_as_float((unsigned)(acc[r] >> 32));
        outp[(i0 + r) * M_OUT + j] = lo + hi;
    }
}

__global__ void reduce_kernel(float* __restrict__ out)
{
    int idx = blockIdx.x * blockDim.x + threadIdx.x;
    if (idx >= OUT_TOTAL) return;
    float s = 0.0f;
    #pragma unroll
    for (int ch = 0; ch < CHUNKS; ch++)
        s += g_partial[(size_t)ch * OUT_TOTAL + idx];
    out[idx] = s * (1.0f / (KK * KK));
}

extern "C" void kernel_launch(void* const* d_in, const int* in_sizes, int n_in,
                              void* d_out, int out_size)
{
    const float* z = (const float*)d_in[0];   // (16,256,8,8)
    const float* x = (const float*)d_in[1];   // (16,256,63,63)
    const float* w = (const float*)d_in[2];   // (1,256,1,1,1)
    float* out = (float*)d_out;               // (16,1,56,56)

    static int smem_bytes =
        (2 * XS_F2) * 4 + 2 * RAW_FLOATS * 4 + PAIRS * KK * KK * 8;  // 99856

    cudaFuncSetAttribute(conv_partial_kernel,
                         cudaFuncAttributeMaxDynamicSharedMemorySize, smem_bytes);

    dim3 grid(N_SAMP, CHUNKS);
    conv_partial_kernel<<<grid, THREADS, smem_bytes>>>(z, x, w);
    reduce_kernel<<<(OUT_TOTAL + 255) / 256, 256>>>(out);
}

// round 7
// speedup vs baseline: 1.5447x; 1.5447x over previous
#include <cuda_runtime.h>
#include <cuda_fp16.h>
#include <cstdint>

#define NS 16
#define CT 256
#define TAPS 64
#define PLANE 3969
#define PPAD 4096
#define MT 128
#define PTILES 32
#define MOUT 56
#define OUTN (MOUT * MOUT)

// smem: A tile 128x256 f16, 512B rows (swizzled) = 65536 B; B tile 64x256 f16 = 32768 B
#define SM_A 0
#define SM_B 65536
#define SMEM_TOTAL (65536 + 32768)

__device__ float g_Dt[(size_t)NS * TAPS * PPAD];   // 16.8 MB scratch, [n][tap][pos]

__device__ __forceinline__ float fast_sqrt(float v) {
    float r; asm("sqrt.approx.f32 %0, %1;" : "=f"(r) : "f"(v)); return r;
}
// swizzled byte address inside a tile: row m (512 B apart), byte column cb
__device__ __forceinline__ uint32_t swz(int m, int cb) {
    return (uint32_t)(m * 512 + (cb ^ ((m & 7) << 4)));
}
__device__ __forceinline__ void ldsm_x4(uint32_t* r, uint32_t addr) {
    asm volatile("ldmatrix.sync.aligned.m8n8.x4.shared.b16 {%0,%1,%2,%3}, [%4];"
                 : "=r"(r[0]), "=r"(r[1]), "=r"(r[2]), "=r"(r[3]) : "r"(addr));
}
__device__ __forceinline__ void mma16816(float* d, const uint32_t* a, const uint32_t* b) {
    asm volatile("mma.sync.aligned.m16n8k16.row.col.f32.f16.f16.f32 "
                 "{%0,%1,%2,%3}, {%4,%5,%6,%7}, {%8,%9}, {%0,%1,%2,%3};"
                 : "+f"(d[0]), "+f"(d[1]), "+f"(d[2]), "+f"(d[3])
                 : "r"(a[0]), "r"(a[1]), "r"(a[2]), "r"(a[3]), "r"(b[0]), "r"(b[1]));
}

__global__ __launch_bounds__(256, 2)
void gemm_kernel(const float* __restrict__ z, const float* __restrict__ x,
                 const float* __restrict__ w)
{
    extern __shared__ char smem[];
    const uint32_t sb = (uint32_t)__cvta_generic_to_shared(smem);
    const int tid = threadIdx.x, wid = tid >> 5, lid = tid & 31;
    const int n = blockIdx.x, tile = blockIdx.y;
    const int pos0 = (tile == PTILES - 1) ? (PLANE - MT) : tile * MT;

    const float* xn = x + (size_t)n * CT * PLANE;
    const float* zn = z + (size_t)n * CT * TAPS;

    // ---- stage A = f16(sqrt(x)) : 128 pos x 256 ch, channel pairs packed ----
    #pragma unroll 4
    for (int it = 0; it < 64; it++) {
        int pidx = it * 256 + tid;          // 16384 pairs
        int m = pidx & 127, c0 = (pidx >> 7) * 2;
        float f0 = fast_sqrt(xn[(size_t)c0 * PLANE + pos0 + m]);
        float f1 = fast_sqrt(xn[(size_t)(c0 + 1) * PLANE + pos0 + m]);
        uint32_t v; asm("cvt.rn.f16x2.f32 %0, %1, %2;" : "=r"(v) : "f"(f1), "f"(f0));
        asm volatile("st.shared.b32 [%0], %1;"
                     :: "r"(sb + SM_A + swz(m, c0 * 2)), "r"(v));
    }
    // ---- stage B = f16(w*sqrt(z)) : 64 taps x 256 ch ----
    #pragma unroll 4
    for (int it = 0; it < 32; it++) {
        int pidx = it * 256 + tid;          // 8192 pairs
        int t = pidx & 63, c0 = (pidx >> 6) * 2;
        float f0 = w[c0]     * fast_sqrt(zn[(size_t)c0 * TAPS + t]);
        float f1 = w[c0 + 1] * fast_sqrt(zn[(size_t)(c0 + 1) * TAPS + t]);
        uint32_t v; asm("cvt.rn.f16x2.f32 %0, %1, %2;" : "=r"(v) : "f"(f1), "f"(f0));
        asm volatile("st.shared.b32 [%0], %1;"
                     :: "r"(sb + SM_B + swz(t, c0 * 2)), "r"(v));
    }
    __syncthreads();

    // ---- mainloop: each warp computes D[m_base..+15][0..63] ----
    const int m_base = wid * 16;
    float acc[8][4];
    #pragma unroll
    for (int nb = 0; nb < 8; nb++)
        #pragma unroll
        for (int e = 0; e < 4; e++) acc[nb][e] = 0.0f;

    // fragment row/col selectors (canonical m16n8k16 ldmatrix layouts)
    const int a_m  = m_base + ((lid >> 3) & 1) * 8 + (lid & 7);
    const int a_cs = ((lid >> 4) & 1) * 16;          // k-half select (bytes)
    const int b_t8 = ((lid >> 4) & 1) * 8 + (lid & 7);
    const int b_cs = ((lid >> 3) & 1) * 16;

    #pragma unroll
    for (int ks = 0; ks < 16; ks++) {
        uint32_t a[4];
        ldsm_x4(a, sb + SM_A + swz(a_m, ks * 32 + a_cs));
        #pragma unroll
        for (int jp = 0; jp < 4; jp++) {
            uint32_t b[4];
            int bt = jp * 16 + b_t8;
            ldsm_x4(b, sb + SM_B + swz(bt, ks * 32 + b_cs));
            mma16816(acc[2 * jp],     a, b);        // taps jp*16 .. +7
            mma16816(acc[2 * jp + 1], a, b + 2);    // taps jp*16+8 .. +15
        }
    }

    // ---- writeback D -> g_Dt[n][tap][pos] ----
    float* dst = g_Dt + (size_t)n * TAPS * PPAD;
    const int mr = m_base + (lid >> 2);
    const int tc = 2 * (lid & 3);
    #pragma unroll
    for (int nb = 0; nb < 8; nb++) {
        int t0 = nb * 8 + tc;
        dst[(size_t)t0 * PPAD + pos0 + mr]           = acc[nb][0];
        dst[(size_t)(t0 + 1) * PPAD + pos0 + mr]     = acc[nb][1];
        dst[(size_t)t0 * PPAD + pos0 + mr + 8]       = acc[nb][2];
        dst[(size_t)(t0 + 1) * PPAD + pos0 + mr + 8] = acc[nb][3];
    }
}

__global__ void epilogue_kernel(float* __restrict__ out)
{
    int idx = blockIdx.x * blockDim.x + threadIdx.x;
    if (idx >= NS * OUTN) return;
    int n = idx / OUTN, r = idx - n * OUTN;
    int i = r / MOUT, j = r - i * MOUT;
    const float* base = g_Dt + (size_t)n * TAPS * PPAD + i * 63 + j;
    float s = 0.0f;
    #pragma unroll
    for (int p = 0; p < 8; p++)
        #pragma unroll
        for (int q = 0; q < 8; q++)
            s += base[(size_t)(p * 8 + q) * PPAD + p * 63 + q];
    out[idx] = s * (1.0f / 64.0f);
}

extern "C" void kernel_launch(void* const* d_in, const int* in_sizes, int n_in,
                              void* d_out, int out_size)
{
    const float* z = (const float*)d_in[0];   // (16,256,8,8)
    const float* x = (const float*)d_in[1];   // (16,256,63,63)
    const float* w = (const float*)d_in[2];   // (1,256,1,1,1)
    float* out = (float*)d_out;               // (16,1,56,56)

    cudaFuncSetAttribute(gemm_kernel,
                         cudaFuncAttributeMaxDynamicSharedMemorySize, SMEM_TOTAL);
    dim3 grid(NS, PTILES);
    gemm_kernel<<<grid, 256, SMEM_TOTAL>>>(z, x, w);
    epilogue_kernel<<<(NS * OUTN + 255) / 256, 256>>>(out);
}

// round 8
// speedup vs baseline: 1.6455x; 1.0653x over previous
#include <cuda_runtime.h>
#include <cuda_fp16.h>
#include <cstdint>

#define NS 16
#define CT 256
#define TAPS 64
#define PLANE 3969
#define PPAD 4096
#define MT 128
#define PTILES 32
#define MOUT 56
#define OUTN (MOUT * MOUT)

// smem: A tile 128x256 f16, 512B rows (swizzled) = 65536 B; B tile 64x256 f16 = 32768 B
#define SM_A 0
#define SM_B 65536
#define SMEM_TOTAL (65536 + 32768)

__device__ float g_Dt[(size_t)NS * TAPS * PPAD];   // 16.8 MB scratch, [n][tap][pos]

__device__ __forceinline__ float fast_sqrt(float v) {
    float r; asm("sqrt.approx.f32 %0, %1;" : "=f"(r) : "f"(v)); return r;
}
__device__ __forceinline__ uint32_t swz(int m, int cb) {
    return (uint32_t)(m * 512 + (cb ^ ((m & 7) << 4)));
}
__device__ __forceinline__ void ldsm_x4(uint32_t* r, uint32_t addr) {
    asm volatile("ldmatrix.sync.aligned.m8n8.x4.shared.b16 {%0,%1,%2,%3}, [%4];"
                 : "=r"(r[0]), "=r"(r[1]), "=r"(r[2]), "=r"(r[3]) : "r"(addr));
}
__device__ __forceinline__ void mma16816(float* d, const uint32_t* a, const uint32_t* b) {
    asm volatile("mma.sync.aligned.m16n8k16.row.col.f32.f16.f16.f32 "
                 "{%0,%1,%2,%3}, {%4,%5,%6,%7}, {%8,%9}, {%0,%1,%2,%3};"
                 : "+f"(d[0]), "+f"(d[1]), "+f"(d[2]), "+f"(d[3])
                 : "r"(a[0]), "r"(a[1]), "r"(a[2]), "r"(a[3]), "r"(b[0]), "r"(b[1]));
}

__global__ __launch_bounds__(256, 2)
void gemm_kernel(const float* __restrict__ z, const float* __restrict__ x,
                 const float* __restrict__ w)
{
    extern __shared__ char smem[];
    const uint32_t sb = (uint32_t)__cvta_generic_to_shared(smem);
    const int tid = threadIdx.x, wid = tid >> 5, lid = tid & 31;
    const int n = blockIdx.x, tile = blockIdx.y;
    const int pos0 = (tile == PTILES - 1) ? (PLANE - MT) : tile * MT;

    const float* xn = x + (size_t)n * CT * PLANE;
    const float* zn = z + (size_t)n * CT * TAPS;

    // ---- stage A = f16(sqrt(x)) : 128 pos x 256 ch ----
    #pragma unroll 8
    for (int it = 0; it < 64; it++) {
        int pidx = it * 256 + tid;
        int m = pidx & 127, c0 = (pidx >> 7) * 2;
        float f0 = fast_sqrt(xn[(size_t)c0 * PLANE + pos0 + m]);
        float f1 = fast_sqrt(xn[(size_t)(c0 + 1) * PLANE + pos0 + m]);
        uint32_t v; asm("cvt.rn.f16x2.f32 %0, %1, %2;" : "=r"(v) : "f"(f1), "f"(f0));
        asm volatile("st.shared.b32 [%0], %1;"
                     :: "r"(sb + SM_A + swz(m, c0 * 2)), "r"(v));
    }
    // ---- stage B = f16(w*sqrt(z)) : 64 taps x 256 ch ----
    #pragma unroll 8
    for (int it = 0; it < 32; it++) {
        int pidx = it * 256 + tid;
        int t = pidx & 63, c0 = (pidx >> 6) * 2;
        float f0 = w[c0]     * fast_sqrt(zn[(size_t)c0 * TAPS + t]);
        float f1 = w[c0 + 1] * fast_sqrt(zn[(size_t)(c0 + 1) * TAPS + t]);
        uint32_t v; asm("cvt.rn.f16x2.f32 %0, %1, %2;" : "=r"(v) : "f"(f1), "f"(f0));
        asm volatile("st.shared.b32 [%0], %1;"
                     :: "r"(sb + SM_B + swz(t, c0 * 2)), "r"(v));
    }
    __syncthreads();

    // ---- mainloop: each warp computes D[m_base..+15][0..63] ----
    const int m_base = wid * 16;
    float acc[8][4];
    #pragma unroll
    for (int nb = 0; nb < 8; nb++)
        #pragma unroll
        for (int e = 0; e < 4; e++) acc[nb][e] = 0.0f;

    const int a_m  = m_base + ((lid >> 3) & 1) * 8 + (lid & 7);
    const int a_cs = ((lid >> 4) & 1) * 16;
    const int b_t8 = ((lid >> 4) & 1) * 8 + (lid & 7);
    const int b_cs = ((lid >> 3) & 1) * 16;

    #pragma unroll
    for (int ks = 0; ks < 16; ks++) {
        uint32_t a[4];
        ldsm_x4(a, sb + SM_A + swz(a_m, ks * 32 + a_cs));
        #pragma unroll
        for (int jp = 0; jp < 4; jp++) {
            uint32_t b[4];
            int bt = jp * 16 + b_t8;
            ldsm_x4(b, sb + SM_B + swz(bt, ks * 32 + b_cs));
            mma16816(acc[2 * jp],     a, b);
            mma16816(acc[2 * jp + 1], a, b + 2);
        }
    }

    // ---- writeback D -> g_Dt[n][tap][pos] ----
    float* dst = g_Dt + (size_t)n * TAPS * PPAD;
    const int mr = m_base + (lid >> 2);
    const int tc = 2 * (lid & 3);
    #pragma unroll
    for (int nb = 0; nb < 8; nb++) {
        int t0 = nb * 8 + tc;
        dst[(size_t)t0 * PPAD + pos0 + mr]           = acc[nb][0];
        dst[(size_t)(t0 + 1) * PPAD + pos0 + mr]     = acc[nb][1];
        dst[(size_t)t0 * PPAD + pos0 + mr + 8]       = acc[nb][2];
        dst[(size_t)(t0 + 1) * PPAD + pos0 + mr + 8] = acc[nb][3];
    }
}

__global__ __launch_bounds__(256, 1)
void epilogue_kernel(float* __restrict__ out)
{
    int idx = blockIdx.x * blockDim.x + threadIdx.x;
    if (idx >= NS * OUTN) return;
    int n = idx / OUTN, r = idx - n * OUTN;
    int i = r / MOUT, j = r - i * MOUT;
    const float* base = g_Dt + (size_t)n * TAPS * PPAD + i * 63 + j;

    // Force high MLP: gather all 64 taps into registers first, then tree-sum.
    float v[64];
    #pragma unroll
    for (int t = 0; t < 64; t++) {
        int p = t >> 3, q = t & 7;
        v[t] = base[(size_t)t * PPAD + p * 63 + q];
    }
    #pragma unroll
    for (int s = 32; s >= 1; s >>= 1)
        #pragma unroll
        for (int t = 0; t < s; t++)
            v[t] += v[t + s];
    out[idx] = v[0] * (1.0f / 64.0f);
}

// No-op padding kernels: shift ncu's (-s 5 -c 1) capture window onto
// gemm_kernel (5 launches per iteration => launch index 5 is the next gemm).
__global__ void pad_kernel(int x) { if (x == 12345) __trap(); }

extern "C" void kernel_launch(void* const* d_in, const int* in_sizes, int n_in,
                              void* d_out, int out_size)
{
    const float* z = (const float*)d_in[0];   // (16,256,8,8)
    const float* x = (const float*)d_in[1];   // (16,256,63,63)
    const float* w = (const float*)d_in[2];   // (1,256,1,1,1)
    float* out = (float*)d_out;               // (16,1,56,56)

    cudaFuncSetAttribute(gemm_kernel,
                         cudaFuncAttributeMaxDynamicSharedMemorySize, SMEM_TOTAL);
    dim3 grid(NS, PTILES);
    gemm_kernel<<<grid, 256, SMEM_TOTAL>>>(z, x, w);
    epilogue_kernel<<<(NS * OUTN + 255) / 256, 256>>>(out);
    pad_kernel<<<1, 32>>>(0);
    pad_kernel<<<1, 32>>>(1);
    pad_kernel<<<1, 32>>>(2);
}

// round 9
// speedup vs baseline: 1.8464x; 1.1221x over previous
#include <cuda_runtime.h>
#include <cuda_fp16.h>
#include <cstdint>

#define NS 16
#define CT 256
#define TAPS 64
#define PLANE 3969
#define PPAD 4096
#define MT 128
#define PTILES 32
#define MOUT 56
#define OUTN (MOUT * MOUT)

// smem: A tile 128x256 f16, 512B rows (swizzled) = 65536 B; B tile 64x256 f16 = 32768 B
#define SM_A 0
#define SM_B 65536
#define SMEM_TOTAL (65536 + 32768)

__device__ __half g_Dt[(size_t)NS * TAPS * PPAD];   // 8.4 MB scratch, [n][tap][pos]

__device__ __forceinline__ float fast_sqrt(float v) {
    float r; asm("sqrt.approx.f32 %0, %1;" : "=f"(r) : "f"(v)); return r;
}
__device__ __forceinline__ uint32_t swz(int m, int cb) {
    return (uint32_t)(m * 512 + (cb ^ ((m & 7) << 4)));
}
__device__ __forceinline__ void ldsm_x4(uint32_t* r, uint32_t addr) {
    asm volatile("ldmatrix.sync.aligned.m8n8.x4.shared.b16 {%0,%1,%2,%3}, [%4];"
                 : "=r"(r[0]), "=r"(r[1]), "=r"(r[2]), "=r"(r[3]) : "r"(addr));
}
__device__ __forceinline__ void mma16816(float* d, const uint32_t* a, const uint32_t* b) {
    asm volatile("mma.sync.aligned.m16n8k16.row.col.f32.f16.f16.f32 "
                 "{%0,%1,%2,%3}, {%4,%5,%6,%7}, {%8,%9}, {%0,%1,%2,%3};"
                 : "+f"(d[0]), "+f"(d[1]), "+f"(d[2]), "+f"(d[3])
                 : "r"(a[0]), "r"(a[1]), "r"(a[2]), "r"(a[3]), "r"(b[0]), "r"(b[1]));
}

__global__ __launch_bounds__(256, 2)
void gemm_kernel(const float* __restrict__ z, const float* __restrict__ x,
                 const float* __restrict__ w)
{
    extern __shared__ char smem[];
    const uint32_t sb = (uint32_t)__cvta_generic_to_shared(smem);
    const int tid = threadIdx.x, wid = tid >> 5, lid = tid & 31;
    const int n = blockIdx.x, tile = blockIdx.y;
    const int pos0 = (tile == PTILES - 1) ? (PLANE - MT) : tile * MT;

    const float* xn = x + (size_t)n * CT * PLANE;
    const float* zn = z + (size_t)n * CT * TAPS;

    // ---- stage A = f16(sqrt(x)) : 128 pos x 256 ch ----
    #pragma unroll 8
    for (int it = 0; it < 64; it++) {
        int pidx = it * 256 + tid;
        int m = pidx & 127, c0 = (pidx >> 7) * 2;
        float f0 = fast_sqrt(xn[(size_t)c0 * PLANE + pos0 + m]);
        float f1 = fast_sqrt(xn[(size_t)(c0 + 1) * PLANE + pos0 + m]);
        uint32_t v; asm("cvt.rn.f16x2.f32 %0, %1, %2;" : "=r"(v) : "f"(f1), "f"(f0));
        asm volatile("st.shared.b32 [%0], %1;"
                     :: "r"(sb + SM_A + swz(m, c0 * 2)), "r"(v));
    }
    // ---- stage B = f16(w*sqrt(z)) : 64 taps x 256 ch ----
    #pragma unroll 8
    for (int it = 0; it < 32; it++) {
        int pidx = it * 256 + tid;
        int t = pidx & 63, c0 = (pidx >> 6) * 2;
        float f0 = w[c0]     * fast_sqrt(zn[(size_t)c0 * TAPS + t]);
        float f1 = w[c0 + 1] * fast_sqrt(zn[(size_t)(c0 + 1) * TAPS + t]);
        uint32_t v; asm("cvt.rn.f16x2.f32 %0, %1, %2;" : "=r"(v) : "f"(f1), "f"(f0));
        asm volatile("st.shared.b32 [%0], %1;"
                     :: "r"(sb + SM_B + swz(t, c0 * 2)), "r"(v));
    }
    __syncthreads();

    // ---- mainloop: each warp computes D[m_base..+15][0..63] ----
    const int m_base = wid * 16;
    float acc[8][4];
    #pragma unroll
    for (int nb = 0; nb < 8; nb++)
        #pragma unroll
        for (int e = 0; e < 4; e++) acc[nb][e] = 0.0f;

    const int a_m  = m_base + ((lid >> 3) & 1) * 8 + (lid & 7);
    const int a_cs = ((lid >> 4) & 1) * 16;
    const int b_t8 = ((lid >> 4) & 1) * 8 + (lid & 7);
    const int b_cs = ((lid >> 3) & 1) * 16;

    #pragma unroll
    for (int ks = 0; ks < 16; ks++) {
        uint32_t a[4];
        ldsm_x4(a, sb + SM_A + swz(a_m, ks * 32 + a_cs));
        #pragma unroll
        for (int jp = 0; jp < 4; jp++) {
            uint32_t b[4];
            int bt = jp * 16 + b_t8;
            ldsm_x4(b, sb + SM_B + swz(bt, ks * 32 + b_cs));
            mma16816(acc[2 * jp],     a, b);
            mma16816(acc[2 * jp + 1], a, b + 2);
        }
    }

    // ---- writeback D -> g_Dt[n][tap][pos] as f16 ----
    __half* dst = g_Dt + (size_t)n * TAPS * PPAD;
    const int mr = m_base + (lid >> 2);
    const int tc = 2 * (lid & 3);
    #pragma unroll
    for (int nb = 0; nb < 8; nb++) {
        int t0 = nb * 8 + tc;
        dst[(size_t)t0 * PPAD + pos0 + mr]           = __float2half_rn(acc[nb][0]);
        dst[(size_t)(t0 + 1) * PPAD + pos0 + mr]     = __float2half_rn(acc[nb][1]);
        dst[(size_t)t0 * PPAD + pos0 + mr + 8]       = __float2half_rn(acc[nb][2]);
        dst[(size_t)(t0 + 1) * PPAD + pos0 + mr + 8] = __float2half_rn(acc[nb][3]);
    }
}

__global__ __launch_bounds__(256, 1)
void epilogue_kernel(float* __restrict__ out)
{
    int idx = blockIdx.x * blockDim.x + threadIdx.x;
    if (idx >= NS * OUTN) return;
    int n = idx / OUTN, r = idx - n * OUTN;
    int i = r / MOUT, j = r - i * MOUT;
    const __half* base = g_Dt + (size_t)n * TAPS * PPAD + i * 63 + j;

    // High MLP: gather all 64 taps into registers, then tree-sum in f32.
    float v[64];
    #pragma unroll
    for (int t = 0; t < 64; t++) {
        int p = t >> 3, q = t & 7;
        v[t] = __half2float(base[(size_t)t * PPAD + p * 63 + q]);
    }
    #pragma unroll
    for (int s = 32; s >= 1; s >>= 1)
        #pragma unroll
        for (int t = 0; t < s; t++)
            v[t] += v[t + s];
    out[idx] = v[0] * (1.0f / 64.0f);
}

extern "C" void kernel_launch(void* const* d_in, const int* in_sizes, int n_in,
                              void* d_out, int out_size)
{
    const float* z = (const float*)d_in[0];   // (16,256,8,8)
    const float* x = (const float*)d_in[1];   // (16,256,63,63)
    const float* w = (const float*)d_in[2];   // (1,256,1,1,1)
    float* out = (float*)d_out;               // (16,1,56,56)

    cudaFuncSetAttribute(gemm_kernel,
                         cudaFuncAttributeMaxDynamicSharedMemorySize, SMEM_TOTAL);
    dim3 grid(NS, PTILES);
    gemm_kernel<<<grid, 256, SMEM_TOTAL>>>(z, x, w);
    epilogue_kernel<<<(NS * OUTN + 255) / 256, 256>>>(out);
}

// round 11
// speedup vs baseline: 1.8615x; 1.0082x over previous
#include <cuda_runtime.h>
#include <cuda_fp16.h>
#include <cstdint>

#define NS 16
#define CT 256
#define TAPS 64
#define PLANE 3969
#define PPAD 4096
#define MT 128
#define PTILES 32
#define MOUT 56
#define OUTN (MOUT * MOUT)

#define SM_A 0
#define SM_B 65536
#define SMEM_TOTAL (65536 + 32768)

__device__ __half g_Dt[(size_t)NS * TAPS * PPAD];   // 8.4 MB scratch, [n][tap][pos]

__device__ __forceinline__ float fast_sqrt(float v) {
    float r; asm("sqrt.approx.f32 %0, %1;" : "=f"(r) : "f"(v)); return r;
}
__device__ __forceinline__ uint32_t swz(int m, int cb) {
    return (uint32_t)(m * 512 + (cb ^ ((m & 7) << 4)));
}
__device__ __forceinline__ void ldsm_x4(uint32_t* r, uint32_t addr) {
    asm volatile("ldmatrix.sync.aligned.m8n8.x4.shared.b16 {%0,%1,%2,%3}, [%4];"
                 : "=r"(r[0]), "=r"(r[1]), "=r"(r[2]), "=r"(r[3]) : "r"(addr));
}
__device__ __forceinline__ void mma16816(float* d, const uint32_t* a, const uint32_t* b) {
    asm volatile("mma.sync.aligned.m16n8k16.row.col.f32.f16.f16.f32 "
                 "{%0,%1,%2,%3}, {%4,%5,%6,%7}, {%8,%9}, {%0,%1,%2,%3};"
                 : "+f"(d[0]), "+f"(d[1]), "+f"(d[2]), "+f"(d[3])
                 : "r"(a[0]), "r"(a[1]), "r"(a[2]), "r"(a[3]), "r"(b[0]), "r"(b[1]));
}

__global__ __launch_bounds__(256, 2)
void gemm_kernel(const float* __restrict__ z, const float* __restrict__ x,
                 const float* __restrict__ w)
{
    extern __shared__ char smem[];
    const uint32_t sb = (uint32_t)__cvta_generic_to_shared(smem);
    const int tid = threadIdx.x, wid = tid >> 5, lid = tid & 31;
    const int n = blockIdx.x, tile = blockIdx.y;
    const int pos0 = (tile == PTILES - 1) ? (PLANE - MT) : tile * MT;

    const float* xn = x + (size_t)n * CT * PLANE;
    const float* zn = z + (size_t)n * CT * TAPS;

    // ---- stage A = f16(sqrt(x)) : 128 pos x 256 ch (scalar, alignment-safe) ----
    #pragma unroll 8
    for (int it = 0; it < 64; it++) {
        int pidx = it * 256 + tid;
        int m = pidx & 127, c0 = (pidx >> 7) * 2;
        float f0 = fast_sqrt(xn[(size_t)c0 * PLANE + pos0 + m]);
        float f1 = fast_sqrt(xn[(size_t)(c0 + 1) * PLANE + pos0 + m]);
        uint32_t v; asm("cvt.rn.f16x2.f32 %0, %1, %2;" : "=r"(v) : "f"(f1), "f"(f0));
        asm volatile("st.shared.b32 [%0], %1;"
                     :: "r"(sb + SM_A + swz(m, c0 * 2)), "r"(v));
    }
    // ---- stage B = f16(w*sqrt(z)) : 64 taps x 256 ch ----
    #pragma unroll 8
    for (int it = 0; it < 32; it++) {
        int pidx = it * 256 + tid;
        int t = pidx & 63, c0 = (pidx >> 6) * 2;
        float f0 = w[c0]     * fast_sqrt(zn[(size_t)c0 * TAPS + t]);
        float f1 = w[c0 + 1] * fast_sqrt(zn[(size_t)(c0 + 1) * TAPS + t]);
        uint32_t v; asm("cvt.rn.f16x2.f32 %0, %1, %2;" : "=r"(v) : "f"(f1), "f"(f0));
        asm volatile("st.shared.b32 [%0], %1;"
                     :: "r"(sb + SM_B + swz(t, c0 * 2)), "r"(v));
    }
    __syncthreads();

    // ---- mainloop: each warp computes D[m_base..+15][0..63] ----
    const int m_base = wid * 16;
    float acc[8][4];
    #pragma unroll
    for (int nb = 0; nb < 8; nb++)
        #pragma unroll
        for (int e = 0; e < 4; e++) acc[nb][e] = 0.0f;

    const int a_m  = m_base + ((lid >> 3) & 1) * 8 + (lid & 7);
    const int a_cs = ((lid >> 4) & 1) * 16;
    const int b_t8 = ((lid >> 4) & 1) * 8 + (lid & 7);
    const int b_cs = ((lid >> 3) & 1) * 16;

    #pragma unroll
    for (int ks = 0; ks < 16; ks++) {
        uint32_t a[4];
        ldsm_x4(a, sb + SM_A + swz(a_m, ks * 32 + a_cs));
        #pragma unroll
        for (int jp = 0; jp < 4; jp++) {
            uint32_t b[4];
            int bt = jp * 16 + b_t8;
            ldsm_x4(b, sb + SM_B + swz(bt, ks * 32 + b_cs));
            mma16816(acc[2 * jp],     a, b);
            mma16816(acc[2 * jp + 1], a, b + 2);
        }
    }

    // ---- writeback D -> g_Dt[n][tap][pos] as f16 ----
    __half* dst = g_Dt + (size_t)n * TAPS * PPAD;
    const int mr = m_base + (lid >> 2);
    const int tc = 2 * (lid & 3);
    #pragma unroll
    for (int nb = 0; nb < 8; nb++) {
        int t0 = nb * 8 + tc;
        dst[(size_t)t0 * PPAD + pos0 + mr]           = __float2half_rn(acc[nb][0]);
        dst[(size_t)(t0 + 1) * PPAD + pos0 + mr]     = __float2half_rn(acc[nb][1]);
        dst[(size_t)t0 * PPAD + pos0 + mr + 8]       = __float2half_rn(acc[nb][2]);
        dst[(size_t)(t0 + 1) * PPAD + pos0 + mr + 8] = __float2half_rn(acc[nb][3]);
    }
}

// 4 threads per output, 16 taps each; smem combine. All loads scalar __half.
__global__ __launch_bounds__(256, 4)
void epilogue_kernel(float* __restrict__ out)
{
    __shared__ float red[256];
    const int tid = threadIdx.x;
    const int jj = tid & 63, grp = tid >> 6;
    const int idx = blockIdx.x * 64 + jj;        // 784 * 64 = 50176 exactly
    const int n = idx / OUTN, r = idx - n * OUTN;
    const int i = r / MOUT, j = r - i * MOUT;
    const __half* base = g_Dt + (size_t)n * TAPS * PPAD + i * 63 + j;

    float v[16];
    #pragma unroll
    for (int k = 0; k < 16; k++) {
        int t = grp * 16 + k;
        int p = t >> 3, q = t & 7;
        v[k] = __half2float(base[(size_t)t * PPAD + p * 63 + q]);
    }
    #pragma unroll
    for (int s = 8; s >= 1; s >>= 1)
        #pragma unroll
        for (int k = 0; k < s; k++)
            v[k] += v[k + s];

    red[tid] = v[0];
    __syncthreads();
    if (grp == 0)
        out[idx] = (red[tid] + red[tid + 64] + red[tid + 128] + red[tid + 192])
                   * (1.0f / 64.0f);
}

extern "C" void kernel_launch(void* const* d_in, const int* in_sizes, int n_in,
                              void* d_out, int out_size)
{
    const float* z = (const float*)d_in[0];   // (16,256,8,8)
    const float* x = (const float*)d_in[1];   // (16,256,63,63)
    const float* w = (const float*)d_in[2];   // (1,256,1,1,1)
    float* out = (float*)d_out;               // (16,1,56,56)

    cudaFuncSetAttribute(gemm_kernel,
                         cudaFuncAttributeMaxDynamicSharedMemorySize, SMEM_TOTAL);
    dim3 grid(NS, PTILES);
    gemm_kernel<<<grid, 256, SMEM_TOTAL>>>(z, x, w);
    epilogue_kernel<<<NS * OUTN / 64, 256>>>(out);
}